// round 3
// baseline (speedup 1.0000x reference)
#include <cuda_runtime.h>
#include <cstdint>

#define NN   100000
#define EE   1600000
#define BBG  64
#define DINV 9
#define HH   128
#define EPSV 1e-5f

#define SCAN_BS 512
#define SCAN_NB ((NN + SCAN_BS - 1) / SCAN_BS)   // 196

#define IST 68    // inT row stride (floats), 16B-aligned rows
#define WST 260   // wdup row stride (floats), 16B-aligned rows

// ---------------- scratch (device globals; no allocation) ----------------
__device__ float    g_h0[NN * HH];
__device__ float    g_h1[NN * HH];
__device__ float    g_agg[NN * HH];
__device__ int      g_rowptr[NN + 1];
__device__ int      g_cursor[NN];
__device__ int      g_cnt[NN];
__device__ int      g_col[EE];
__device__ int      g_bsum[256];
__device__ float    g_gsum[BBG * HH];
__device__ unsigned g_gmax[BBG * HH];
__device__ int      g_gcnt[BBG];

// ---------------- packed f32x2 helpers ----------------
__device__ __forceinline__ void fma2(unsigned long long& d,
                                     unsigned long long a,
                                     unsigned long long b)
{
    asm("fma.rn.f32x2 %0, %1, %2, %0;" : "+l"(d) : "l"(a), "l"(b));
}
__device__ __forceinline__ float lo32(unsigned long long v) {
    return __uint_as_float((unsigned)v);
}
__device__ __forceinline__ float hi32(unsigned long long v) {
    return __uint_as_float((unsigned)(v >> 32));
}

// ---------------- epilogue: LayerNorm + ReLU + store ----------------
// One warp holds all 128 features of a node: lane l owns features 4l..4l+3.
__device__ __forceinline__ void ln_relu_store(float4 acc, int node, int lane,
                                              float4 gv, float4 bev,
                                              float* __restrict__ out, int nNodes)
{
    float s = acc.x + acc.y + acc.z + acc.w;
    float q = acc.x * acc.x + acc.y * acc.y + acc.z * acc.z + acc.w * acc.w;
#pragma unroll
    for (int off = 16; off; off >>= 1) {
        s += __shfl_xor_sync(0xffffffffu, s, off);
        q += __shfl_xor_sync(0xffffffffu, q, off);
    }
    float m  = s * (1.0f / HH);
    float v  = q * (1.0f / HH) - m * m;
    float rs = rsqrtf(v + EPSV);
    float4 y;
    y.x = fmaxf((acc.x - m) * rs * gv.x + bev.x, 0.0f);
    y.y = fmaxf((acc.y - m) * rs * gv.y + bev.y, 0.0f);
    y.z = fmaxf((acc.z - m) * rs * gv.z + bev.z, 0.0f);
    y.w = fmaxf((acc.w - m) * rs * gv.w + bev.w, 0.0f);
    if (node < nNodes)
        *(float4*)(out + (size_t)node * HH + lane * 4) = y;
}

// ---------------- node embedder: relu(LN(x @ W0^T + b0)) ----------------
// Also zeroes g_cnt (fused, runs before k_count).
__global__ void k_embed(const float* __restrict__ x, const float* __restrict__ W0,
                        const float* __restrict__ b0, const float* __restrict__ g0,
                        const float* __restrict__ be0, float* __restrict__ out, int nNodes)
{
    __shared__ float w0S[DINV * 132];
    __shared__ float xS[64 * DINV];

    int tid  = threadIdx.x;
    int lane = tid & 31, warp = tid >> 5;
    int node0 = blockIdx.x * 64;

    int zi = blockIdx.x * 256 + tid;          // fused g_cnt zeroing
    if (zi < NN) g_cnt[zi] = 0;

    for (int i = tid; i < DINV * HH; i += blockDim.x) {
        int k = i / HH, o = i % HH;
        w0S[k * 132 + o] = W0[o * DINV + k];
    }
    for (int i = tid; i < 64 * DINV; i += blockDim.x) {
        int gidx = node0 * DINV + i;
        xS[i] = (gidx < nNodes * DINV) ? x[gidx] : 0.0f;
    }
    __syncthreads();

    float4 acc[8];
#pragma unroll
    for (int n = 0; n < 8; n++) acc[n] = make_float4(0.f, 0.f, 0.f, 0.f);

    int nb = warp * 8;
#pragma unroll
    for (int k = 0; k < DINV; k++) {
        float4 wv = *(const float4*)(w0S + k * 132 + lane * 4);
#pragma unroll
        for (int n = 0; n < 8; n++) {
            float a = xS[(nb + n) * DINV + k];
            acc[n].x += a * wv.x; acc[n].y += a * wv.y;
            acc[n].z += a * wv.z; acc[n].w += a * wv.w;
        }
    }

    float4 bv  = *(const float4*)(b0 + lane * 4);
    float4 gv  = *(const float4*)(g0 + lane * 4);
    float4 bev = *(const float4*)(be0 + lane * 4);
#pragma unroll
    for (int n = 0; n < 8; n++) {
        acc[n].x += bv.x; acc[n].y += bv.y; acc[n].z += bv.z; acc[n].w += bv.w;
        ln_relu_store(acc[n], node0 + nb + n, lane, gv, bev, out, nNodes);
    }
}

// ---------------- CSR build ----------------
__global__ void k_count(const int* __restrict__ dst) {
    int e = blockIdx.x * blockDim.x + threadIdx.x;
    if (e < EE) atomicAdd(&g_cnt[dst[e]], 1);
}

__global__ void k_scan1() {
    __shared__ int s[SCAN_BS];
    int t = threadIdx.x;
    int i = blockIdx.x * SCAN_BS + t;
    int val = (i < NN) ? g_cnt[i] : 0;
    s[t] = val;
    __syncthreads();
#pragma unroll
    for (int off = 1; off < SCAN_BS; off <<= 1) {
        int xx = (t >= off) ? s[t - off] : 0;
        __syncthreads();
        s[t] += xx;
        __syncthreads();
    }
    if (i < NN) g_rowptr[i + 1] = s[t];          // raw inclusive (no block offset yet)
    if (t == SCAN_BS - 1) g_bsum[blockIdx.x] = s[t];
}

// parallel block scan (replaces serial 1-thread loop)
__global__ void k_scan2() {
    __shared__ int s[256];
    int t = threadIdx.x;
    int v = (t < SCAN_NB) ? g_bsum[t] : 0;
    s[t] = v;
    __syncthreads();
#pragma unroll
    for (int off = 1; off < 256; off <<= 1) {
        int xx = (t >= off) ? s[t - off] : 0;
        __syncthreads();
        s[t] += xx;
        __syncthreads();
    }
    if (t < SCAN_NB) g_bsum[t] = s[t] - v;   // exclusive
    if (t == 0) g_rowptr[0] = 0;
}

// add block offsets; also derive cursor[i] = rowptr[i] = incl - cnt[i]
__global__ void k_scan3() {
    for (int i = blockIdx.x * blockDim.x + threadIdx.x; i < NN; i += gridDim.x * blockDim.x) {
        int incl = g_rowptr[i + 1] + g_bsum[i / SCAN_BS];
        g_rowptr[i + 1] = incl;
        g_cursor[i] = incl - g_cnt[i];
    }
}

// fill CSR; also zeroes the pooling buffers (fused)
__global__ void k_fill(const int* __restrict__ src, const int* __restrict__ dst) {
    int e = blockIdx.x * blockDim.x + threadIdx.x;
    if (e < BBG * HH) { g_gsum[e] = 0.0f; g_gmax[e] = 0u; }
    if (e < BBG) g_gcnt[e] = 0;
    if (e < EE) {
        int d = dst[e];
        int p = atomicAdd(&g_cursor[d], 1);
        g_col[p] = src[e];
    }
}

// ---------------- pull-based mean aggregation ----------------
__global__ void k_agg(const float* __restrict__ hin, float* __restrict__ agg) {
    int node = blockIdx.x * 2 + (threadIdx.x >> 7);
    int f    = threadIdx.x & 127;
    int beg = g_rowptr[node], end = g_rowptr[node + 1];
    float s = 0.0f;
    int j = beg;
    for (; j + 4 <= end; j += 4) {
        int c0 = g_col[j], c1 = g_col[j + 1], c2 = g_col[j + 2], c3 = g_col[j + 3];
        s += hin[(size_t)c0 * HH + f];
        s += hin[(size_t)c1 * HH + f];
        s += hin[(size_t)c2 * HH + f];
        s += hin[(size_t)c3 * HH + f];
    }
    for (; j < end; j++) s += hin[(size_t)g_col[j] * HH + f];
    float d = (float)(end - beg);
    agg[(size_t)node * HH + f] = s / fmaxf(d, 1.0f);
}

// ---------------- fused dual-GEMM + LN + ReLU (packed f32x2) ----------------
// out = relu(LN(agg@Wl^T + bl + h@Wr^T)); tile 64 nodes x 128 feats, 256 threads.
// Warp w -> nodes 8w..8w+7 (as 4 packed pairs); lane l -> features 4l..4l+3.
__global__ void __launch_bounds__(256)
k_gemm_ln(const float* __restrict__ A, const float* __restrict__ Hin,
          const float* __restrict__ Wl, const float* __restrict__ bl,
          const float* __restrict__ Wr,
          const float* __restrict__ gam, const float* __restrict__ bet,
          float* __restrict__ out, int nNodes)
{
    __shared__ float inT[32 * IST];      // transposed input tile [k][node]
    __shared__ float wdup[32 * WST];     // duplicated weights [k][{w,w} per feature]

    int tid  = threadIdx.x;
    int lane = tid & 31, warp = tid >> 5;
    int node0 = blockIdx.x * 64;
    int nb = warp * 8;

    unsigned long long acc[4][4];        // [feature 0..3][node-pair 0..3]
#pragma unroll
    for (int fi = 0; fi < 4; fi++)
#pragma unroll
        for (int p = 0; p < 4; p++) acc[fi][p] = 0ULL;

#pragma unroll 1
    for (int c = 0; c < 8; c++) {
        const float* srcp = (c < 4) ? A : Hin;
        const float* W    = (c < 4) ? Wl : Wr;
        int k0 = (c & 3) * 32;

        // stage input transposed: inT[kk][node]
        {
            int r  = tid >> 3;            // node within tile (0..31), +32 on 2nd iter
            int c4 = (tid & 7) * 4;       // kk base
#pragma unroll
            for (int it = 0; it < 2; it++) {
                int row  = r + it * 32;
                int node = node0 + row;
                if (node >= nNodes) node = nNodes - 1;
                float4 v = *(const float4*)(srcp + (size_t)node * HH + k0 + c4);
                inT[(c4 + 0) * IST + row] = v.x;
                inT[(c4 + 1) * IST + row] = v.y;
                inT[(c4 + 2) * IST + row] = v.z;
                inT[(c4 + 3) * IST + row] = v.w;
            }
        }
        // stage duplicated weights: wdup[kk][2*o] = wdup[kk][2*o+1] = W[o][k0+kk]
        {
            int kk4 = (tid & 7) * 4;
            int o0  = tid >> 3;
#pragma unroll
            for (int it = 0; it < 4; it++) {
                int o = o0 + it * 32;
                float4 v = *(const float4*)(W + o * HH + k0 + kk4);
                *(float2*)(wdup + (kk4 + 0) * WST + 2 * o) = make_float2(v.x, v.x);
                *(float2*)(wdup + (kk4 + 1) * WST + 2 * o) = make_float2(v.y, v.y);
                *(float2*)(wdup + (kk4 + 2) * WST + 2 * o) = make_float2(v.z, v.z);
                *(float2*)(wdup + (kk4 + 3) * WST + 2 * o) = make_float2(v.w, v.w);
            }
        }
        __syncthreads();

#pragma unroll
        for (int kk = 0; kk < 32; kk++) {
            ulonglong2 a01 = *(const ulonglong2*)(inT + kk * IST + nb);      // pairs 0,1
            ulonglong2 a23 = *(const ulonglong2*)(inT + kk * IST + nb + 4);  // pairs 2,3
            ulonglong2 w01 = *(const ulonglong2*)(wdup + kk * WST + lane * 8);     // f0,f1
            ulonglong2 w23 = *(const ulonglong2*)(wdup + kk * WST + lane * 8 + 4); // f2,f3

            fma2(acc[0][0], a01.x, w01.x); fma2(acc[0][1], a01.y, w01.x);
            fma2(acc[0][2], a23.x, w01.x); fma2(acc[0][3], a23.y, w01.x);
            fma2(acc[1][0], a01.x, w01.y); fma2(acc[1][1], a01.y, w01.y);
            fma2(acc[1][2], a23.x, w01.y); fma2(acc[1][3], a23.y, w01.y);
            fma2(acc[2][0], a01.x, w23.x); fma2(acc[2][1], a01.y, w23.x);
            fma2(acc[2][2], a23.x, w23.x); fma2(acc[2][3], a23.y, w23.x);
            fma2(acc[3][0], a01.x, w23.y); fma2(acc[3][1], a01.y, w23.y);
            fma2(acc[3][2], a23.x, w23.y); fma2(acc[3][3], a23.y, w23.y);
        }
        __syncthreads();
    }

    float4 bv  = *(const float4*)(bl + lane * 4);
    float4 gv  = *(const float4*)(gam + lane * 4);
    float4 bev = *(const float4*)(bet + lane * 4);
#pragma unroll
    for (int n = 0; n < 8; n++) {
        int p = n >> 1;
        float4 a;
        if (n & 1) {
            a.x = hi32(acc[0][p]); a.y = hi32(acc[1][p]);
            a.z = hi32(acc[2][p]); a.w = hi32(acc[3][p]);
        } else {
            a.x = lo32(acc[0][p]); a.y = lo32(acc[1][p]);
            a.z = lo32(acc[2][p]); a.w = lo32(acc[3][p]);
        }
        a.x += bv.x; a.y += bv.y; a.z += bv.z; a.w += bv.w;
        ln_relu_store(a, node0 + nb + n, lane, gv, bev, out, nNodes);
    }
}

// ---------------- pooling (register-accumulated; batch is sorted) ----------------
__global__ void k_pool(const float* __restrict__ ne, const int* __restrict__ batch) {
    int base = blockIdx.x * 128;
    int sub  = threadIdx.x >> 7;      // 0/1
    int f    = threadIdx.x & 127;
    float s = 0.0f, mx = 0.0f;
    int cur = -1, cnt = 0;
    for (int i = sub; i < 128; i += 2) {
        int node = base + i;
        if (node >= NN) break;
        int b = batch[node];
        if (b != cur) {
            if (cur >= 0) {
                atomicAdd(&g_gsum[cur * HH + f], s);
                atomicMax(&g_gmax[cur * HH + f], __float_as_uint(mx));
                if (f == 0) atomicAdd(&g_gcnt[cur], cnt);
            }
            cur = b; s = 0.0f; mx = 0.0f; cnt = 0;
        }
        float v = ne[(size_t)node * HH + f];
        s += v; mx = fmaxf(mx, v); cnt++;
    }
    if (cur >= 0) {
        atomicAdd(&g_gsum[cur * HH + f], s);
        atomicMax(&g_gmax[cur * HH + f], __float_as_uint(mx));
        if (f == 0) atomicAdd(&g_gcnt[cur], cnt);
    }
}

__global__ void k_pool_final(float* __restrict__ out) {
    int b = blockIdx.x, f = threadIdx.x;
    float cnt = fmaxf((float)g_gcnt[b], 1.0f);
    out[(size_t)NN * HH + b * 2 * HH + f]      = g_gsum[b * HH + f] / cnt;
    out[(size_t)NN * HH + b * 2 * HH + HH + f] = __uint_as_float(g_gmax[b * HH + f]);
}

// ---------------- launch ----------------
extern "C" void kernel_launch(void* const* d_in, const int* in_sizes, int n_in,
                              void* d_out, int out_size)
{
    const float* x    = (const float*)d_in[0];
    const int*   ei   = (const int*)d_in[1];
    const int*   bat  = (const int*)d_in[2];
    const float* W0   = (const float*)d_in[3];
    const float* b0   = (const float*)d_in[4];
    const float* g0   = (const float*)d_in[5];
    const float* be0  = (const float*)d_in[6];
    const float* Wl1  = (const float*)d_in[7];
    const float* bl1  = (const float*)d_in[8];
    const float* Wr1  = (const float*)d_in[9];
    const float* g1   = (const float*)d_in[10];
    const float* be1  = (const float*)d_in[11];
    const float* Wl2  = (const float*)d_in[12];
    const float* bl2  = (const float*)d_in[13];
    const float* Wr2  = (const float*)d_in[14];
    const float* g2   = (const float*)d_in[15];
    const float* be2  = (const float*)d_in[16];
    const float* Wl3  = (const float*)d_in[17];
    const float* bl3  = (const float*)d_in[18];
    const float* Wr3  = (const float*)d_in[19];
    const float* g3   = (const float*)d_in[20];
    const float* be3  = (const float*)d_in[21];
    float* out = (float*)d_out;

    const int* src = ei;        // edge_index[0]
    const int* dst = ei + EE;   // edge_index[1]

    float* h0;  cudaGetSymbolAddress((void**)&h0,  g_h0);
    float* h1;  cudaGetSymbolAddress((void**)&h1,  g_h1);
    float* agg; cudaGetSymbolAddress((void**)&agg, g_agg);

    int nodeBlocks = (NN + 63) / 64;          // 1563
    int edgeBlocks = (EE + 255) / 256;        // 6250

    // node embedder -> h0 (also zeroes g_cnt)
    k_embed<<<nodeBlocks, 256>>>(x, W0, b0, g0, be0, h0, NN);

    // CSR build (dst-indexed)
    k_count<<<edgeBlocks, 256>>>(dst);
    k_scan1<<<SCAN_NB, SCAN_BS>>>();
    k_scan2<<<1, 256>>>();
    k_scan3<<<256, 256>>>();
    k_fill<<<edgeBlocks, 256>>>(src, dst);    // also zeroes pooling buffers

    // layer 1: h0 -> h1
    k_agg<<<NN / 2, 256>>>(h0, agg);
    k_gemm_ln<<<nodeBlocks, 256>>>(agg, h0, Wl1, bl1, Wr1, g1, be1, h1, NN);
    // layer 2: h1 -> h0
    k_agg<<<NN / 2, 256>>>(h1, agg);
    k_gemm_ln<<<nodeBlocks, 256>>>(agg, h1, Wl2, bl2, Wr2, g2, be2, h0, NN);
    // layer 3: h0 -> node_embed (d_out)
    k_agg<<<NN / 2, 256>>>(h0, agg);
    k_gemm_ln<<<nodeBlocks, 256>>>(agg, h0, Wl3, bl3, Wr3, g3, be3, out, NN);

    // pooling
    k_pool<<<(NN + 127) / 128, 256>>>(out, bat);
    k_pool_final<<<BBG, HH>>>(out);
}

// round 9
// speedup vs baseline: 1.9257x; 1.9257x over previous
#include <cuda_runtime.h>
#include <cstdint>

#define NN   100000
#define EE   1600000
#define BBG  64
#define DINV 9
#define HH   128
#define EPSV 1e-5f

#define SCAN_BS 512
#define SCAN_NB ((NN + SCAN_BS - 1) / SCAN_BS)   // 196

#define AST 36   // smem row stride (floats); 144B rows, 16B-aligned

// ---------------- scratch (device globals; no allocation) ----------------
__device__ float    g_h0[NN * HH];
__device__ float    g_h1[NN * HH];
__device__ float    g_agg[NN * HH];
__device__ int      g_rowptr[NN + 1];
__device__ int      g_cursor[NN];
__device__ int      g_cnt[NN];
__device__ int      g_col[EE];
__device__ int      g_bsum[256];
__device__ float    g_gsum[BBG * HH];
__device__ unsigned g_gmax[BBG * HH];
__device__ int      g_gcnt[BBG];

// ---------------- helpers ----------------
__device__ __forceinline__ float to_tf32(float x) {
    float r; asm("cvt.rna.tf32.f32 %0, %1;" : "=f"(r) : "f"(x)); return r;
}

__device__ __forceinline__ void mma_tf32(float* c, uint32_t a0, uint32_t a1,
                                         uint32_t a2, uint32_t a3,
                                         uint32_t b0, uint32_t b1)
{
    asm volatile(
        "mma.sync.aligned.m16n8k8.row.col.f32.tf32.tf32.f32 "
        "{%0,%1,%2,%3}, {%4,%5,%6,%7}, {%8,%9}, {%0,%1,%2,%3};\n"
        : "+f"(c[0]), "+f"(c[1]), "+f"(c[2]), "+f"(c[3])
        : "r"(a0), "r"(a1), "r"(a2), "r"(a3), "r"(b0), "r"(b1));
}

// permuted store of 8 consecutive K values: [k0,k4,k1,k5,k2,k6,k3,k7]
__device__ __forceinline__ void store_perm8(float* base, float4 lo, float4 hi) {
    float4 p0, p1;
    p0.x = to_tf32(lo.x); p0.y = to_tf32(hi.x);
    p0.z = to_tf32(lo.y); p0.w = to_tf32(hi.y);
    p1.x = to_tf32(lo.z); p1.y = to_tf32(hi.z);
    p1.z = to_tf32(lo.w); p1.w = to_tf32(hi.w);
    *(float4*)(base)     = p0;
    *(float4*)(base + 4) = p1;
}

// ---------------- epilogue helper (scalar kernels) ----------------
__device__ __forceinline__ void ln_relu_store(float4 acc, int node, int lane,
                                              float4 gv, float4 bev,
                                              float* __restrict__ out, int nNodes)
{
    float s = acc.x + acc.y + acc.z + acc.w;
    float q = acc.x * acc.x + acc.y * acc.y + acc.z * acc.z + acc.w * acc.w;
#pragma unroll
    for (int off = 16; off; off >>= 1) {
        s += __shfl_xor_sync(0xffffffffu, s, off);
        q += __shfl_xor_sync(0xffffffffu, q, off);
    }
    float m  = s * (1.0f / HH);
    float v  = q * (1.0f / HH) - m * m;
    float rs = rsqrtf(v + EPSV);
    float4 y;
    y.x = fmaxf((acc.x - m) * rs * gv.x + bev.x, 0.0f);
    y.y = fmaxf((acc.y - m) * rs * gv.y + bev.y, 0.0f);
    y.z = fmaxf((acc.z - m) * rs * gv.z + bev.z, 0.0f);
    y.w = fmaxf((acc.w - m) * rs * gv.w + bev.w, 0.0f);
    if (node < nNodes)
        *(float4*)(out + (size_t)node * HH + lane * 4) = y;
}

// ---------------- node embedder (also zeroes g_cnt) ----------------
__global__ void k_embed(const float* __restrict__ x, const float* __restrict__ W0,
                        const float* __restrict__ b0, const float* __restrict__ g0,
                        const float* __restrict__ be0, float* __restrict__ out, int nNodes)
{
    __shared__ float w0S[DINV * 132];
    __shared__ float xS[64 * DINV];

    int tid  = threadIdx.x;
    int lane = tid & 31, warp = tid >> 5;
    int node0 = blockIdx.x * 64;

    int zi = blockIdx.x * 256 + tid;
    if (zi < NN) g_cnt[zi] = 0;

    for (int i = tid; i < DINV * HH; i += blockDim.x) {
        int k = i / HH, o = i % HH;
        w0S[k * 132 + o] = W0[o * DINV + k];
    }
    for (int i = tid; i < 64 * DINV; i += blockDim.x) {
        int gidx = node0 * DINV + i;
        xS[i] = (gidx < nNodes * DINV) ? x[gidx] : 0.0f;
    }
    __syncthreads();

    float4 acc[8];
#pragma unroll
    for (int n = 0; n < 8; n++) acc[n] = make_float4(0.f, 0.f, 0.f, 0.f);

    int nb = warp * 8;
#pragma unroll
    for (int k = 0; k < DINV; k++) {
        float4 wv = *(const float4*)(w0S + k * 132 + lane * 4);
#pragma unroll
        for (int n = 0; n < 8; n++) {
            float a = xS[(nb + n) * DINV + k];
            acc[n].x += a * wv.x; acc[n].y += a * wv.y;
            acc[n].z += a * wv.z; acc[n].w += a * wv.w;
        }
    }

    float4 bv  = *(const float4*)(b0 + lane * 4);
    float4 gv  = *(const float4*)(g0 + lane * 4);
    float4 bev = *(const float4*)(be0 + lane * 4);
#pragma unroll
    for (int n = 0; n < 8; n++) {
        acc[n].x += bv.x; acc[n].y += bv.y; acc[n].z += bv.z; acc[n].w += bv.w;
        ln_relu_store(acc[n], node0 + nb + n, lane, gv, bev, out, nNodes);
    }
}

// ---------------- CSR build ----------------
__global__ void k_count(const int* __restrict__ dst) {
    int e = blockIdx.x * blockDim.x + threadIdx.x;
    if (e < EE) atomicAdd(&g_cnt[dst[e]], 1);
}

__global__ void k_scan1() {
    __shared__ int s[SCAN_BS];
    int t = threadIdx.x;
    int i = blockIdx.x * SCAN_BS + t;
    int val = (i < NN) ? g_cnt[i] : 0;
    s[t] = val;
    __syncthreads();
#pragma unroll
    for (int off = 1; off < SCAN_BS; off <<= 1) {
        int xx = (t >= off) ? s[t - off] : 0;
        __syncthreads();
        s[t] += xx;
        __syncthreads();
    }
    if (i < NN) g_rowptr[i + 1] = s[t];
    if (t == SCAN_BS - 1) g_bsum[blockIdx.x] = s[t];
}

__global__ void k_scan23() {
    __shared__ int s[256];
    __shared__ int e[256];
    int t = threadIdx.x;
    int v = (t < SCAN_NB) ? g_bsum[t] : 0;
    s[t] = v;
    __syncthreads();
#pragma unroll
    for (int off = 1; off < 256; off <<= 1) {
        int xx = (t >= off) ? s[t - off] : 0;
        __syncthreads();
        s[t] += xx;
        __syncthreads();
    }
    e[t] = s[t] - v;
    __syncthreads();
    for (int i = blockIdx.x * blockDim.x + t; i < NN; i += gridDim.x * blockDim.x) {
        int incl = g_rowptr[i + 1] + e[i / SCAN_BS];
        g_rowptr[i + 1] = incl;
        g_cursor[i] = incl - g_cnt[i];
    }
    if (blockIdx.x == 0 && t == 0) g_rowptr[0] = 0;
}

__global__ void k_fill(const int* __restrict__ src, const int* __restrict__ dst) {
    int e = blockIdx.x * blockDim.x + threadIdx.x;
    if (e < BBG * HH) { g_gsum[e] = 0.0f; g_gmax[e] = 0u; }
    if (e < BBG) g_gcnt[e] = 0;
    if (e < EE) {
        int d = dst[e];
        int p = atomicAdd(&g_cursor[d], 1);
        g_col[p] = src[e];
    }
}

// ---------------- pull-based mean aggregation ----------------
__global__ void k_agg(const float* __restrict__ hin, float* __restrict__ agg) {
    int node = blockIdx.x * 2 + (threadIdx.x >> 7);
    int f    = threadIdx.x & 127;
    int beg = g_rowptr[node], end = g_rowptr[node + 1];
    float s = 0.0f;
    int j = beg;
    for (; j + 4 <= end; j += 4) {
        int c0 = g_col[j], c1 = g_col[j + 1], c2 = g_col[j + 2], c3 = g_col[j + 3];
        s += hin[(size_t)c0 * HH + f];
        s += hin[(size_t)c1 * HH + f];
        s += hin[(size_t)c2 * HH + f];
        s += hin[(size_t)c3 * HH + f];
    }
    for (; j < end; j++) s += hin[(size_t)g_col[j] * HH + f];
    float d = (float)(end - beg);
    agg[(size_t)node * HH + f] = s / fmaxf(d, 1.0f);
}

// ---------------- tf32 mma.sync dual-GEMM + LN + ReLU ----------------
// CTA: 128 nodes x 128 out-feats, K=256 (agg||h vs Wl||Wr), 8 warps in 2x4.
// Warp tile 64x32. m16n8k8 tf32 fragments, pair-permuted smem K layout.
__global__ void __launch_bounds__(256, 2)
k_gemm_mma(const float* __restrict__ A, const float* __restrict__ Hin,
           const float* __restrict__ Wl, const float* __restrict__ bl,
           const float* __restrict__ Wr,
           const float* __restrict__ gam, const float* __restrict__ bet,
           float* __restrict__ out, int nNodes)
{
    __shared__ float As[128 * AST];
    __shared__ float Bs[128 * AST];
    __shared__ float2 stats[4][128];

    int tid  = threadIdx.x;
    int lane = tid & 31, wid = tid >> 5;
    int warp_m = wid >> 2;           // 0..1
    int warp_n = wid & 3;            // 0..3
    int node0 = blockIdx.x * 128;
    int gq = lane >> 2;              // group (0..7)
    int tq = lane & 3;               // thread-in-group (0..3)

    float acc[4][4][4];
#pragma unroll
    for (int m = 0; m < 4; m++)
#pragma unroll
        for (int n = 0; n < 4; n++)
#pragma unroll
            for (int r = 0; r < 4; r++) acc[m][n][r] = 0.0f;

#pragma unroll 1
    for (int c = 0; c < 8; c++) {
        const float* srcA = (c < 4) ? A : Hin;
        const float* W    = (c < 4) ? Wl : Wr;
        int k0 = (c & 3) * 32;

        // stage A + B: 512 groups-of-8 each, 2 per thread
#pragma unroll
        for (int it = 0; it < 2; it++) {
            int gi  = it * 256 + tid;     // 0..511
            int row = gi >> 2;
            int g   = gi & 3;
            int nodeIdx = node0 + row;
            if (nodeIdx >= nNodes) nodeIdx = nNodes - 1;
            const float* pa = srcA + (size_t)nodeIdx * HH + k0 + g * 8;
            store_perm8(As + row * AST + g * 8, *(const float4*)pa, *(const float4*)(pa + 4));
            const float* pb = W + (size_t)row * HH + k0 + g * 8;
            store_perm8(Bs + row * AST + g * 8, *(const float4*)pb, *(const float4*)(pb + 4));
        }
        __syncthreads();

#pragma unroll
        for (int s = 0; s < 4; s++) {
            uint32_t b0[4], b1[4];
#pragma unroll
            for (int n = 0; n < 4; n++) {
                float2 bv = *(const float2*)(Bs + (warp_n * 32 + n * 8 + gq) * AST + s * 8 + tq * 2);
                b0[n] = __float_as_uint(bv.x);
                b1[n] = __float_as_uint(bv.y);
            }
#pragma unroll
            for (int m = 0; m < 4; m++) {
                int rbase = warp_m * 64 + m * 16 + gq;
                float2 a02 = *(const float2*)(As + rbase * AST + s * 8 + tq * 2);
                float2 a13 = *(const float2*)(As + (rbase + 8) * AST + s * 8 + tq * 2);
                uint32_t ra0 = __float_as_uint(a02.x);
                uint32_t ra1 = __float_as_uint(a13.x);
                uint32_t ra2 = __float_as_uint(a02.y);
                uint32_t ra3 = __float_as_uint(a13.y);
#pragma unroll
                for (int n = 0; n < 4; n++)
                    mma_tf32(acc[m][n], ra0, ra1, ra2, ra3, b0[n], b1[n]);
            }
        }
        __syncthreads();
    }

    // ---- epilogue: bias + LN + ReLU ----
    float blv[4][2], gmv[4][2], btv[4][2];
#pragma unroll
    for (int n = 0; n < 4; n++) {
        int col = warp_n * 32 + n * 8 + 2 * tq;
        blv[n][0] = __ldg(bl + col);  blv[n][1] = __ldg(bl + col + 1);
        gmv[n][0] = __ldg(gam + col); gmv[n][1] = __ldg(gam + col + 1);
        btv[n][0] = __ldg(bet + col); btv[n][1] = __ldg(bet + col + 1);
    }

    // add bias; per-row partial sums; quad reduce; write stats
#pragma unroll
    for (int m = 0; m < 4; m++) {
#pragma unroll
        for (int rh = 0; rh < 2; rh++) {
            float s = 0.0f, q = 0.0f;
#pragma unroll
            for (int n = 0; n < 4; n++) {
                float v0 = acc[m][n][rh * 2 + 0] + blv[n][0];
                float v1 = acc[m][n][rh * 2 + 1] + blv[n][1];
                acc[m][n][rh * 2 + 0] = v0;
                acc[m][n][rh * 2 + 1] = v1;
                s += v0 + v1; q += v0 * v0 + v1 * v1;
            }
            s += __shfl_xor_sync(0xffffffffu, s, 1);
            q += __shfl_xor_sync(0xffffffffu, q, 1);
            s += __shfl_xor_sync(0xffffffffu, s, 2);
            q += __shfl_xor_sync(0xffffffffu, q, 2);
            if (tq == 0)
                stats[warp_n][warp_m * 64 + m * 16 + rh * 8 + gq] = make_float2(s, q);
        }
    }
    __syncthreads();

    if (tid < 128) {
        float2 p0 = stats[0][tid], p1 = stats[1][tid];
        float2 p2 = stats[2][tid], p3 = stats[3][tid];
        float s = p0.x + p1.x + p2.x + p3.x;
        float q = p0.y + p1.y + p2.y + p3.y;
        float m  = s * (1.0f / HH);
        float vv = q * (1.0f / HH) - m * m;
        stats[0][tid] = make_float2(m, rsqrtf(vv + EPSV));
    }
    __syncthreads();

#pragma unroll
    for (int m = 0; m < 4; m++) {
#pragma unroll
        for (int rh = 0; rh < 2; rh++) {
            int row = warp_m * 64 + m * 16 + rh * 8 + gq;
            int node = node0 + row;
            if (node >= nNodes) continue;
            float2 mr = stats[0][row];
            float mu = mr.x, rs = mr.y;
#pragma unroll
            for (int n = 0; n < 4; n++) {
                int col = warp_n * 32 + n * 8 + 2 * tq;
                float y0 = fmaxf((acc[m][n][rh * 2 + 0] - mu) * rs * gmv[n][0] + btv[n][0], 0.0f);
                float y1 = fmaxf((acc[m][n][rh * 2 + 1] - mu) * rs * gmv[n][1] + btv[n][1], 0.0f);
                *(float2*)(out + (size_t)node * HH + col) = make_float2(y0, y1);
            }
        }
    }
}

// ---------------- pooling (register-accumulated; batch is sorted) ----------------
__global__ void k_pool(const float* __restrict__ ne, const int* __restrict__ batch) {
    int base = blockIdx.x * 128;
    int sub  = threadIdx.x >> 7;
    int f    = threadIdx.x & 127;
    float s = 0.0f, mx = 0.0f;
    int cur = -1, cnt = 0;
    for (int i = sub; i < 128; i += 2) {
        int node = base + i;
        if (node >= NN) break;
        int b = batch[node];
        if (b != cur) {
            if (cur >= 0) {
                atomicAdd(&g_gsum[cur * HH + f], s);
                atomicMax(&g_gmax[cur * HH + f], __float_as_uint(mx));
                if (f == 0) atomicAdd(&g_gcnt[cur], cnt);
            }
            cur = b; s = 0.0f; mx = 0.0f; cnt = 0;
        }
        float v = ne[(size_t)node * HH + f];
        s += v; mx = fmaxf(mx, v); cnt++;
    }
    if (cur >= 0) {
        atomicAdd(&g_gsum[cur * HH + f], s);
        atomicMax(&g_gmax[cur * HH + f], __float_as_uint(mx));
        if (f == 0) atomicAdd(&g_gcnt[cur], cnt);
    }
}

__global__ void k_pool_final(float* __restrict__ out) {
    int b = blockIdx.x, f = threadIdx.x;
    float cnt = fmaxf((float)g_gcnt[b], 1.0f);
    out[(size_t)NN * HH + b * 2 * HH + f]      = g_gsum[b * HH + f] / cnt;
    out[(size_t)NN * HH + b * 2 * HH + HH + f] = __uint_as_float(g_gmax[b * HH + f]);
}

// ---------------- launch ----------------
extern "C" void kernel_launch(void* const* d_in, const int* in_sizes, int n_in,
                              void* d_out, int out_size)
{
    const float* x    = (const float*)d_in[0];
    const int*   ei   = (const int*)d_in[1];
    const int*   bat  = (const int*)d_in[2];
    const float* W0   = (const float*)d_in[3];
    const float* b0   = (const float*)d_in[4];
    const float* g0   = (const float*)d_in[5];
    const float* be0  = (const float*)d_in[6];
    const float* Wl1  = (const float*)d_in[7];
    const float* bl1  = (const float*)d_in[8];
    const float* Wr1  = (const float*)d_in[9];
    const float* g1   = (const float*)d_in[10];
    const float* be1  = (const float*)d_in[11];
    const float* Wl2  = (const float*)d_in[12];
    const float* bl2  = (const float*)d_in[13];
    const float* Wr2  = (const float*)d_in[14];
    const float* g2   = (const float*)d_in[15];
    const float* be2  = (const float*)d_in[16];
    const float* Wl3  = (const float*)d_in[17];
    const float* bl3  = (const float*)d_in[18];
    const float* Wr3  = (const float*)d_in[19];
    const float* g3   = (const float*)d_in[20];
    const float* be3  = (const float*)d_in[21];
    float* out = (float*)d_out;

    const int* src = ei;
    const int* dst = ei + EE;

    float* h0;  cudaGetSymbolAddress((void**)&h0,  g_h0);
    float* h1;  cudaGetSymbolAddress((void**)&h1,  g_h1);
    float* agg; cudaGetSymbolAddress((void**)&agg, g_agg);

    int nodeBlocks64  = (NN + 63) / 64;        // 1563
    int nodeBlocks128 = (NN + 127) / 128;      // 782
    int edgeBlocks    = (EE + 255) / 256;      // 6250

    k_embed<<<nodeBlocks64, 256>>>(x, W0, b0, g0, be0, h0, NN);

    k_count<<<edgeBlocks, 256>>>(dst);
    k_scan1<<<SCAN_NB, SCAN_BS>>>();
    k_scan23<<<256, 256>>>();
    k_fill<<<edgeBlocks, 256>>>(src, dst);

    // layer 1: h0 -> h1
    k_agg<<<NN / 2, 256>>>(h0, agg);
    k_gemm_mma<<<nodeBlocks128, 256>>>(agg, h0, Wl1, bl1, Wr1, g1, be1, h1, NN);
    // layer 2: h1 -> h0
    k_agg<<<NN / 2, 256>>>(h1, agg);
    k_gemm_mma<<<nodeBlocks128, 256>>>(agg, h1, Wl2, bl2, Wr2, g2, be2, h0, NN);
    // layer 3: h0 -> node_embed (d_out)
    k_agg<<<NN / 2, 256>>>(h0, agg);
    k_gemm_mma<<<nodeBlocks128, 256>>>(agg, h0, Wl3, bl3, Wr3, g3, be3, out, NN);

    // pooling
    k_pool<<<(NN + 127) / 128, 256>>>(out, bat);
    k_pool_final<<<BBG, HH>>>(out);
}

// round 12
// speedup vs baseline: 2.9389x; 1.5261x over previous
#include <cuda_runtime.h>
#include <cstdint>

#define NN   100000
#define EE   1600000
#define BBG  64
#define DINV 9
#define HH   128
#define EPSV 1e-5f

#define SCAN_BS 512
#define SCAN_NB ((NN + SCAN_BS - 1) / SCAN_BS)   // 196

#define AST 36   // smem row stride (floats); 144B rows, 16B-aligned

// ---------------- scratch (device globals; no allocation) ----------------
__device__ float    g_h0[NN * HH];
__device__ float    g_h1[NN * HH];
__device__ float    g_agg[NN * HH];
__device__ int      g_rowptr[NN + 1];
__device__ int      g_cursor[NN];
__device__ int      g_cnt[NN];
__device__ int      g_col[EE];
__device__ int      g_bsum[256];
__device__ float    g_gsum[BBG * HH];
__device__ unsigned g_gmax[BBG * HH];
__device__ int      g_gcnt[BBG];

// ---------------- helpers ----------------
__device__ __forceinline__ float to_tf32(float x) {
    float r; asm("cvt.rna.tf32.f32 %0, %1;" : "=f"(r) : "f"(x)); return r;
}

__device__ __forceinline__ void mma_tf32(float* c, uint32_t a0, uint32_t a1,
                                         uint32_t a2, uint32_t a3,
                                         uint32_t b0, uint32_t b1)
{
    asm volatile(
        "mma.sync.aligned.m16n8k8.row.col.f32.tf32.tf32.f32 "
        "{%0,%1,%2,%3}, {%4,%5,%6,%7}, {%8,%9}, {%0,%1,%2,%3};\n"
        : "+f"(c[0]), "+f"(c[1]), "+f"(c[2]), "+f"(c[3])
        : "r"(a0), "r"(a1), "r"(a2), "r"(a3), "r"(b0), "r"(b1));
}

// permuted store of 8 consecutive K values: [k0,k4,k1,k5,k2,k6,k3,k7]
__device__ __forceinline__ void store_perm8(float* base, float4 lo, float4 hi) {
    float4 p0, p1;
    p0.x = to_tf32(lo.x); p0.y = to_tf32(hi.x);
    p0.z = to_tf32(lo.y); p0.w = to_tf32(hi.y);
    p1.x = to_tf32(lo.z); p1.y = to_tf32(hi.z);
    p1.z = to_tf32(lo.w); p1.w = to_tf32(hi.w);
    *(float4*)(base)     = p0;
    *(float4*)(base + 4) = p1;
}

// ---------------- epilogue helper (scalar kernels) ----------------
__device__ __forceinline__ void ln_relu_store(float4 acc, int node, int lane,
                                              float4 gv, float4 bev,
                                              float* __restrict__ out, int nNodes)
{
    float s = acc.x + acc.y + acc.z + acc.w;
    float q = acc.x * acc.x + acc.y * acc.y + acc.z * acc.z + acc.w * acc.w;
#pragma unroll
    for (int off = 16; off; off >>= 1) {
        s += __shfl_xor_sync(0xffffffffu, s, off);
        q += __shfl_xor_sync(0xffffffffu, q, off);
    }
    float m  = s * (1.0f / HH);
    float v  = q * (1.0f / HH) - m * m;
    float rs = rsqrtf(v + EPSV);
    float4 y;
    y.x = fmaxf((acc.x - m) * rs * gv.x + bev.x, 0.0f);
    y.y = fmaxf((acc.y - m) * rs * gv.y + bev.y, 0.0f);
    y.z = fmaxf((acc.z - m) * rs * gv.z + bev.z, 0.0f);
    y.w = fmaxf((acc.w - m) * rs * gv.w + bev.w, 0.0f);
    if (node < nNodes)
        *(float4*)(out + (size_t)node * HH + lane * 4) = y;
}

// ---------------- node embedder (also zeroes g_cnt) ----------------
__global__ void k_embed(const float* __restrict__ x, const float* __restrict__ W0,
                        const float* __restrict__ b0, const float* __restrict__ g0,
                        const float* __restrict__ be0, float* __restrict__ out, int nNodes)
{
    __shared__ float w0S[DINV * 132];
    __shared__ float xS[64 * DINV];

    int tid  = threadIdx.x;
    int lane = tid & 31, warp = tid >> 5;
    int node0 = blockIdx.x * 64;

    int zi = blockIdx.x * 256 + tid;
    if (zi < NN) g_cnt[zi] = 0;

    for (int i = tid; i < DINV * HH; i += blockDim.x) {
        int k = i / HH, o = i % HH;
        w0S[k * 132 + o] = W0[o * DINV + k];
    }
    for (int i = tid; i < 64 * DINV; i += blockDim.x) {
        int gidx = node0 * DINV + i;
        xS[i] = (gidx < nNodes * DINV) ? x[gidx] : 0.0f;
    }
    __syncthreads();

    float4 acc[8];
#pragma unroll
    for (int n = 0; n < 8; n++) acc[n] = make_float4(0.f, 0.f, 0.f, 0.f);

    int nb = warp * 8;
#pragma unroll
    for (int k = 0; k < DINV; k++) {
        float4 wv = *(const float4*)(w0S + k * 132 + lane * 4);
#pragma unroll
        for (int n = 0; n < 8; n++) {
            float a = xS[(nb + n) * DINV + k];
            acc[n].x += a * wv.x; acc[n].y += a * wv.y;
            acc[n].z += a * wv.z; acc[n].w += a * wv.w;
        }
    }

    float4 bv  = *(const float4*)(b0 + lane * 4);
    float4 gv  = *(const float4*)(g0 + lane * 4);
    float4 bev = *(const float4*)(be0 + lane * 4);
#pragma unroll
    for (int n = 0; n < 8; n++) {
        acc[n].x += bv.x; acc[n].y += bv.y; acc[n].z += bv.z; acc[n].w += bv.w;
        ln_relu_store(acc[n], node0 + nb + n, lane, gv, bev, out, nNodes);
    }
}

// ---------------- CSR build ----------------
__global__ void k_count(const int* __restrict__ dst) {
    int e = blockIdx.x * blockDim.x + threadIdx.x;
    if (e < EE) atomicAdd(&g_cnt[dst[e]], 1);
}

__global__ void k_scan1() {
    __shared__ int s[SCAN_BS];
    int t = threadIdx.x;
    int i = blockIdx.x * SCAN_BS + t;
    int val = (i < NN) ? g_cnt[i] : 0;
    s[t] = val;
    __syncthreads();
#pragma unroll
    for (int off = 1; off < SCAN_BS; off <<= 1) {
        int xx = (t >= off) ? s[t - off] : 0;
        __syncthreads();
        s[t] += xx;
        __syncthreads();
    }
    if (i < NN) g_rowptr[i + 1] = s[t];
    if (t == SCAN_BS - 1) g_bsum[blockIdx.x] = s[t];
}

__global__ void k_scan23() {
    __shared__ int s[256];
    __shared__ int e[256];
    int t = threadIdx.x;
    int v = (t < SCAN_NB) ? g_bsum[t] : 0;
    s[t] = v;
    __syncthreads();
#pragma unroll
    for (int off = 1; off < 256; off <<= 1) {
        int xx = (t >= off) ? s[t - off] : 0;
        __syncthreads();
        s[t] += xx;
        __syncthreads();
    }
    e[t] = s[t] - v;
    __syncthreads();
    for (int i = blockIdx.x * blockDim.x + t; i < NN; i += gridDim.x * blockDim.x) {
        int incl = g_rowptr[i + 1] + e[i / SCAN_BS];
        g_rowptr[i + 1] = incl;
        g_cursor[i] = incl - g_cnt[i];
    }
    if (blockIdx.x == 0 && t == 0) g_rowptr[0] = 0;
}

__global__ void k_fill(const int* __restrict__ src, const int* __restrict__ dst) {
    int e = blockIdx.x * blockDim.x + threadIdx.x;
    if (e < BBG * HH) { g_gsum[e] = 0.0f; g_gmax[e] = 0u; }
    if (e < BBG) g_gcnt[e] = 0;
    if (e < EE) {
        int d = dst[e];
        int p = atomicAdd(&g_cursor[d], 1);
        g_col[p] = src[e];
    }
}

// ---------------- pull-based mean aggregation (warp per node, float4) ----------------
__global__ void __launch_bounds__(256)
k_agg(const float* __restrict__ hin, float* __restrict__ agg) {
    int node = blockIdx.x * 8 + (threadIdx.x >> 5);
    int lane = threadIdx.x & 31;
    int beg = g_rowptr[node], end = g_rowptr[node + 1];
    float4 s = make_float4(0.f, 0.f, 0.f, 0.f);
    int j = beg;
#pragma unroll 1
    for (; j + 4 <= end; j += 4) {
        int c0 = g_col[j], c1 = g_col[j + 1], c2 = g_col[j + 2], c3 = g_col[j + 3];
        float4 v0 = *(const float4*)(hin + (size_t)c0 * HH + lane * 4);
        float4 v1 = *(const float4*)(hin + (size_t)c1 * HH + lane * 4);
        float4 v2 = *(const float4*)(hin + (size_t)c2 * HH + lane * 4);
        float4 v3 = *(const float4*)(hin + (size_t)c3 * HH + lane * 4);
        s.x += (v0.x + v1.x) + (v2.x + v3.x);
        s.y += (v0.y + v1.y) + (v2.y + v3.y);
        s.z += (v0.z + v1.z) + (v2.z + v3.z);
        s.w += (v0.w + v1.w) + (v2.w + v3.w);
    }
#pragma unroll 1
    for (; j < end; j++) {
        int c = g_col[j];
        float4 v = *(const float4*)(hin + (size_t)c * HH + lane * 4);
        s.x += v.x; s.y += v.y; s.z += v.z; s.w += v.w;
    }
    float inv = 1.0f / fmaxf((float)(end - beg), 1.0f);
    float4 o = make_float4(s.x * inv, s.y * inv, s.z * inv, s.w * inv);
    *(float4*)(agg + (size_t)node * HH + lane * 4) = o;
}

// ---------------- tf32 mma.sync dual-GEMM + LN + ReLU ----------------
// CTA: 128 nodes x 128 out-feats, K=256 (agg||h vs Wl||Wr), 8 warps in 2x4.
// Warp tile 64x32. m16n8k8 tf32 fragments, pair-permuted smem K layout.
// A operand is register-prefetched one chunk ahead; B (weights) is L1-hot.
__global__ void __launch_bounds__(256, 2)
k_gemm_mma(const float* __restrict__ A, const float* __restrict__ Hin,
           const float* __restrict__ Wl, const float* __restrict__ bl,
           const float* __restrict__ Wr,
           const float* __restrict__ gam, const float* __restrict__ bet,
           float* __restrict__ out, int nNodes)
{
    __shared__ float As[128 * AST];
    __shared__ float Bs[128 * AST];
    __shared__ float2 stats[4][128];

    int tid  = threadIdx.x;
    int lane = tid & 31, wid = tid >> 5;
    int warp_m = wid >> 2;           // 0..1
    int warp_n = wid & 3;            // 0..3
    int node0 = blockIdx.x * 128;
    int gq = lane >> 2;              // group (0..7)
    int tq = lane & 3;               // thread-in-group (0..3)

    // staging index (constant per thread): two groups, gi = it*256+tid
    int srow[2], sg[2], snode[2];
#pragma unroll
    for (int it = 0; it < 2; it++) {
        int gi = it * 256 + tid;
        srow[it] = gi >> 2;
        sg[it]   = gi & 3;
        int nd = node0 + srow[it];
        snode[it] = (nd >= nNodes) ? (nNodes - 1) : nd;
    }

    float acc[4][4][4];
#pragma unroll
    for (int m = 0; m < 4; m++)
#pragma unroll
        for (int n = 0; n < 4; n++)
#pragma unroll
            for (int r = 0; r < 4; r++) acc[m][n][r] = 0.0f;

    // prefetch chunk 0 of A
    float4 paLo[2], paHi[2];
#pragma unroll
    for (int it = 0; it < 2; it++) {
        const float* pa = A + (size_t)snode[it] * HH + sg[it] * 8;
        paLo[it] = *(const float4*)pa;
        paHi[it] = *(const float4*)(pa + 4);
    }

#pragma unroll 1
    for (int c = 0; c < 8; c++) {
        const float* W = (c < 4) ? Wl : Wr;
        int k0 = (c & 3) * 32;

        // store prefetched A; stage B inline
#pragma unroll
        for (int it = 0; it < 2; it++) {
            store_perm8(As + srow[it] * AST + sg[it] * 8, paLo[it], paHi[it]);
            const float* pb = W + (size_t)srow[it] * HH + k0 + sg[it] * 8;
            store_perm8(Bs + srow[it] * AST + sg[it] * 8,
                        *(const float4*)pb, *(const float4*)(pb + 4));
        }
        __syncthreads();

        // prefetch next chunk of A (overlaps the MMA loop below)
        if (c < 7) {
            int cn = c + 1;
            const float* srcA = (cn < 4) ? A : Hin;
            int k0n = (cn & 3) * 32;
#pragma unroll
            for (int it = 0; it < 2; it++) {
                const float* pa = srcA + (size_t)snode[it] * HH + k0n + sg[it] * 8;
                paLo[it] = *(const float4*)pa;
                paHi[it] = *(const float4*)(pa + 4);
            }
        }

#pragma unroll
        for (int s = 0; s < 4; s++) {
            uint32_t b0[4], b1[4];
#pragma unroll
            for (int n = 0; n < 4; n++) {
                float2 bv = *(const float2*)(Bs + (warp_n * 32 + n * 8 + gq) * AST + s * 8 + tq * 2);
                b0[n] = __float_as_uint(bv.x);
                b1[n] = __float_as_uint(bv.y);
            }
#pragma unroll
            for (int m = 0; m < 4; m++) {
                int rbase = warp_m * 64 + m * 16 + gq;
                float2 a02 = *(const float2*)(As + rbase * AST + s * 8 + tq * 2);
                float2 a13 = *(const float2*)(As + (rbase + 8) * AST + s * 8 + tq * 2);
                uint32_t ra0 = __float_as_uint(a02.x);
                uint32_t ra1 = __float_as_uint(a13.x);
                uint32_t ra2 = __float_as_uint(a02.y);
                uint32_t ra3 = __float_as_uint(a13.y);
#pragma unroll
                for (int n = 0; n < 4; n++)
                    mma_tf32(acc[m][n], ra0, ra1, ra2, ra3, b0[n], b1[n]);
            }
        }
        __syncthreads();
    }

    // ---- epilogue: bias + LN + ReLU ----
    float blv[4][2], gmv[4][2], btv[4][2];
#pragma unroll
    for (int n = 0; n < 4; n++) {
        int col = warp_n * 32 + n * 8 + 2 * tq;
        blv[n][0] = __ldg(bl + col);  blv[n][1] = __ldg(bl + col + 1);
        gmv[n][0] = __ldg(gam + col); gmv[n][1] = __ldg(gam + col + 1);
        btv[n][0] = __ldg(bet + col); btv[n][1] = __ldg(bet + col + 1);
    }

#pragma unroll
    for (int m = 0; m < 4; m++) {
#pragma unroll
        for (int rh = 0; rh < 2; rh++) {
            float s = 0.0f, q = 0.0f;
#pragma unroll
            for (int n = 0; n < 4; n++) {
                float v0 = acc[m][n][rh * 2 + 0] + blv[n][0];
                float v1 = acc[m][n][rh * 2 + 1] + blv[n][1];
                acc[m][n][rh * 2 + 0] = v0;
                acc[m][n][rh * 2 + 1] = v1;
                s += v0 + v1; q += v0 * v0 + v1 * v1;
            }
            s += __shfl_xor_sync(0xffffffffu, s, 1);
            q += __shfl_xor_sync(0xffffffffu, q, 1);
            s += __shfl_xor_sync(0xffffffffu, s, 2);
            q += __shfl_xor_sync(0xffffffffu, q, 2);
            if (tq == 0)
                stats[warp_n][warp_m * 64 + m * 16 + rh * 8 + gq] = make_float2(s, q);
        }
    }
    __syncthreads();

    if (tid < 128) {
        float2 p0 = stats[0][tid], p1 = stats[1][tid];
        float2 p2 = stats[2][tid], p3 = stats[3][tid];
        float s = p0.x + p1.x + p2.x + p3.x;
        float q = p0.y + p1.y + p2.y + p3.y;
        float m  = s * (1.0f / HH);
        float vv = q * (1.0f / HH) - m * m;
        stats[0][tid] = make_float2(m, rsqrtf(vv + EPSV));
    }
    __syncthreads();

#pragma unroll
    for (int m = 0; m < 4; m++) {
#pragma unroll
        for (int rh = 0; rh < 2; rh++) {
            int row = warp_m * 64 + m * 16 + rh * 8 + gq;
            int node = node0 + row;
            if (node >= nNodes) continue;
            float2 mr = stats[0][row];
            float mu = mr.x, rs = mr.y;
#pragma unroll
            for (int n = 0; n < 4; n++) {
                int col = warp_n * 32 + n * 8 + 2 * tq;
                float y0 = fmaxf((acc[m][n][rh * 2 + 0] - mu) * rs * gmv[n][0] + btv[n][0], 0.0f);
                float y1 = fmaxf((acc[m][n][rh * 2 + 1] - mu) * rs * gmv[n][1] + btv[n][1], 0.0f);
                *(float2*)(out + (size_t)node * HH + col) = make_float2(y0, y1);
            }
        }
    }
}

// ---------------- pooling (register-accumulated; batch is sorted) ----------------
__global__ void k_pool(const float* __restrict__ ne, const int* __restrict__ batch) {
    int base = blockIdx.x * 128;
    int sub  = threadIdx.x >> 7;
    int f    = threadIdx.x & 127;
    float s = 0.0f, mx = 0.0f;
    int cur = -1, cnt = 0;
    for (int i = sub; i < 128; i += 2) {
        int node = base + i;
        if (node >= NN) break;
        int b = batch[node];
        if (b != cur) {
            if (cur >= 0) {
                atomicAdd(&g_gsum[cur * HH + f], s);
                atomicMax(&g_gmax[cur * HH + f], __float_as_uint(mx));
                if (f == 0) atomicAdd(&g_gcnt[cur], cnt);
            }
            cur = b; s = 0.0f; mx = 0.0f; cnt = 0;
        }
        float v = ne[(size_t)node * HH + f];
        s += v; mx = fmaxf(mx, v); cnt++;
    }
    if (cur >= 0) {
        atomicAdd(&g_gsum[cur * HH + f], s);
        atomicMax(&g_gmax[cur * HH + f], __float_as_uint(mx));
        if (f == 0) atomicAdd(&g_gcnt[cur], cnt);
    }
}

__global__ void k_pool_final(float* __restrict__ out) {
    int b = blockIdx.x, f = threadIdx.x;
    float cnt = fmaxf((float)g_gcnt[b], 1.0f);
    out[(size_t)NN * HH + b * 2 * HH + f]      = g_gsum[b * HH + f] / cnt;
    out[(size_t)NN * HH + b * 2 * HH + HH + f] = __uint_as_float(g_gmax[b * HH + f]);
}

// ---------------- launch ----------------
extern "C" void kernel_launch(void* const* d_in, const int* in_sizes, int n_in,
                              void* d_out, int out_size)
{
    const float* x    = (const float*)d_in[0];
    const int*   ei   = (const int*)d_in[1];
    const int*   bat  = (const int*)d_in[2];
    const float* W0   = (const float*)d_in[3];
    const float* b0   = (const float*)d_in[4];
    const float* g0   = (const float*)d_in[5];
    const float* be0  = (const float*)d_in[6];
    const float* Wl1  = (const float*)d_in[7];
    const float* bl1  = (const float*)d_in[8];
    const float* Wr1  = (const float*)d_in[9];
    const float* g1   = (const float*)d_in[10];
    const float* be1  = (const float*)d_in[11];
    const float* Wl2  = (const float*)d_in[12];
    const float* bl2  = (const float*)d_in[13];
    const float* Wr2  = (const float*)d_in[14];
    const float* g2   = (const float*)d_in[15];
    const float* be2  = (const float*)d_in[16];
    const float* Wl3  = (const float*)d_in[17];
    const float* bl3  = (const float*)d_in[18];
    const float* Wr3  = (const float*)d_in[19];
    const float* g3   = (const float*)d_in[20];
    const float* be3  = (const float*)d_in[21];
    float* out = (float*)d_out;

    const int* src = ei;
    const int* dst = ei + EE;

    float* h0;  cudaGetSymbolAddress((void**)&h0,  g_h0);
    float* h1;  cudaGetSymbolAddress((void**)&h1,  g_h1);
    float* agg; cudaGetSymbolAddress((void**)&agg, g_agg);

    int nodeBlocks64  = (NN + 63) / 64;        // 1563
    int nodeBlocks128 = (NN + 127) / 128;      // 782
    int edgeBlocks    = (EE + 255) / 256;      // 6250
    int aggBlocks     = (NN + 7) / 8;          // 12500

    k_embed<<<nodeBlocks64, 256>>>(x, W0, b0, g0, be0, h0, NN);

    k_count<<<edgeBlocks, 256>>>(dst);
    k_scan1<<<SCAN_NB, SCAN_BS>>>();
    k_scan23<<<256, 256>>>();
    k_fill<<<edgeBlocks, 256>>>(src, dst);

    // layer 1: h0 -> h1
    k_agg<<<aggBlocks, 256>>>(h0, agg);
    k_gemm_mma<<<nodeBlocks128, 256>>>(agg, h0, Wl1, bl1, Wr1, g1, be1, h1, NN);
    // layer 2: h1 -> h0
    k_agg<<<aggBlocks, 256>>>(h1, agg);
    k_gemm_mma<<<nodeBlocks128, 256>>>(agg, h1, Wl2, bl2, Wr2, g2, be2, h0, NN);
    // layer 3: h0 -> node_embed (d_out)
    k_agg<<<aggBlocks, 256>>>(h0, agg);
    k_gemm_mma<<<nodeBlocks128, 256>>>(agg, h0, Wl3, bl3, Wr3, g3, be3, out, NN);

    // pooling
    k_pool<<<(NN + 127) / 128, 256>>>(out, bat);
    k_pool_final<<<BBG, HH>>>(out);
}

// round 13
// speedup vs baseline: 3.0785x; 1.0475x over previous
#include <cuda_runtime.h>
#include <cuda_bf16.h>
#include <cstdint>

#define NN   100000
#define EE   1600000
#define BBG  64
#define DINV 9
#define HH   128
#define EPSV 1e-5f

#define SCAN_BS 512
#define SCAN_NB ((NN + SCAN_BS - 1) / SCAN_BS)   // 196

#define AST 36   // smem row stride (floats); 144B rows, 16B-aligned

// ---------------- scratch (device globals; no allocation) ----------------
__device__ float          g_h0[NN * HH];
__device__ float          g_h1[NN * HH];
__device__ float          g_agg[NN * HH];
__device__ __nv_bfloat162 g_hb[NN * (HH / 2)];   // bf16 mirror for gather
__device__ int      g_rowptr[NN + 1];
__device__ int      g_cursor[NN];
__device__ int      g_cnt[NN];
__device__ int      g_col[EE];
__device__ int      g_bsum[256];
__device__ float    g_gsum[BBG * HH];
__device__ unsigned g_gmax[BBG * HH];
__device__ int      g_gcnt[BBG];

// ---------------- helpers ----------------
__device__ __forceinline__ float to_tf32(float x) {
    float r; asm("cvt.rna.tf32.f32 %0, %1;" : "=f"(r) : "f"(x)); return r;
}

__device__ __forceinline__ void mma_tf32(float* c, uint32_t a0, uint32_t a1,
                                         uint32_t a2, uint32_t a3,
                                         uint32_t b0, uint32_t b1)
{
    asm volatile(
        "mma.sync.aligned.m16n8k8.row.col.f32.tf32.tf32.f32 "
        "{%0,%1,%2,%3}, {%4,%5,%6,%7}, {%8,%9}, {%0,%1,%2,%3};\n"
        : "+f"(c[0]), "+f"(c[1]), "+f"(c[2]), "+f"(c[3])
        : "r"(a0), "r"(a1), "r"(a2), "r"(a3), "r"(b0), "r"(b1));
}

// permuted store of 8 consecutive K values: [k0,k4,k1,k5,k2,k6,k3,k7]
__device__ __forceinline__ void store_perm8(float* base, float4 lo, float4 hi) {
    float4 p0, p1;
    p0.x = to_tf32(lo.x); p0.y = to_tf32(hi.x);
    p0.z = to_tf32(lo.y); p0.w = to_tf32(hi.y);
    p1.x = to_tf32(lo.z); p1.y = to_tf32(hi.z);
    p1.z = to_tf32(lo.w); p1.w = to_tf32(hi.w);
    *(float4*)(base)     = p0;
    *(float4*)(base + 4) = p1;
}

// ---------------- epilogue helper (embed kernel) ----------------
__device__ __forceinline__ void ln_relu_store(float4 acc, int node, int lane,
                                              float4 gv, float4 bev,
                                              float* __restrict__ out,
                                              __nv_bfloat162* __restrict__ outb,
                                              int nNodes)
{
    float s = acc.x + acc.y + acc.z + acc.w;
    float q = acc.x * acc.x + acc.y * acc.y + acc.z * acc.z + acc.w * acc.w;
#pragma unroll
    for (int off = 16; off; off >>= 1) {
        s += __shfl_xor_sync(0xffffffffu, s, off);
        q += __shfl_xor_sync(0xffffffffu, q, off);
    }
    float m  = s * (1.0f / HH);
    float v  = q * (1.0f / HH) - m * m;
    float rs = rsqrtf(v + EPSV);
    float4 y;
    y.x = fmaxf((acc.x - m) * rs * gv.x + bev.x, 0.0f);
    y.y = fmaxf((acc.y - m) * rs * gv.y + bev.y, 0.0f);
    y.z = fmaxf((acc.z - m) * rs * gv.z + bev.z, 0.0f);
    y.w = fmaxf((acc.w - m) * rs * gv.w + bev.w, 0.0f);
    if (node < nNodes) {
        *(float4*)(out + (size_t)node * HH + lane * 4) = y;
        __nv_bfloat162 b0 = __floats2bfloat162_rn(y.x, y.y);
        __nv_bfloat162 b1 = __floats2bfloat162_rn(y.z, y.w);
        *(uint2*)(outb + (size_t)node * (HH / 2) + lane * 2) =
            make_uint2(*(uint32_t*)&b0, *(uint32_t*)&b1);
    }
}

// ---------------- node embedder (also zeroes g_cnt) ----------------
__global__ void k_embed(const float* __restrict__ x, const float* __restrict__ W0,
                        const float* __restrict__ b0, const float* __restrict__ g0,
                        const float* __restrict__ be0, float* __restrict__ out,
                        __nv_bfloat162* __restrict__ outb, int nNodes)
{
    __shared__ float w0S[DINV * 132];
    __shared__ float xS[64 * DINV];

    int tid  = threadIdx.x;
    int lane = tid & 31, warp = tid >> 5;
    int node0 = blockIdx.x * 64;

    int zi = blockIdx.x * 256 + tid;
    if (zi < NN) g_cnt[zi] = 0;

    for (int i = tid; i < DINV * HH; i += blockDim.x) {
        int k = i / HH, o = i % HH;
        w0S[k * 132 + o] = W0[o * DINV + k];
    }
    for (int i = tid; i < 64 * DINV; i += blockDim.x) {
        int gidx = node0 * DINV + i;
        xS[i] = (gidx < nNodes * DINV) ? x[gidx] : 0.0f;
    }
    __syncthreads();

    float4 acc[8];
#pragma unroll
    for (int n = 0; n < 8; n++) acc[n] = make_float4(0.f, 0.f, 0.f, 0.f);

    int nb = warp * 8;
#pragma unroll
    for (int k = 0; k < DINV; k++) {
        float4 wv = *(const float4*)(w0S + k * 132 + lane * 4);
#pragma unroll
        for (int n = 0; n < 8; n++) {
            float a = xS[(nb + n) * DINV + k];
            acc[n].x += a * wv.x; acc[n].y += a * wv.y;
            acc[n].z += a * wv.z; acc[n].w += a * wv.w;
        }
    }

    float4 bv  = *(const float4*)(b0 + lane * 4);
    float4 gv  = *(const float4*)(g0 + lane * 4);
    float4 bev = *(const float4*)(be0 + lane * 4);
#pragma unroll
    for (int n = 0; n < 8; n++) {
        acc[n].x += bv.x; acc[n].y += bv.y; acc[n].z += bv.z; acc[n].w += bv.w;
        ln_relu_store(acc[n], node0 + nb + n, lane, gv, bev, out, outb, nNodes);
    }
}

// ---------------- CSR build ----------------
__global__ void k_count(const int* __restrict__ dst) {
    int e = blockIdx.x * blockDim.x + threadIdx.x;
    if (e < EE) atomicAdd(&g_cnt[dst[e]], 1);
}

__global__ void k_scan1() {
    __shared__ int s[SCAN_BS];
    int t = threadIdx.x;
    int i = blockIdx.x * SCAN_BS + t;
    int val = (i < NN) ? g_cnt[i] : 0;
    s[t] = val;
    __syncthreads();
#pragma unroll
    for (int off = 1; off < SCAN_BS; off <<= 1) {
        int xx = (t >= off) ? s[t - off] : 0;
        __syncthreads();
        s[t] += xx;
        __syncthreads();
    }
    if (i < NN) g_rowptr[i + 1] = s[t];
    if (t == SCAN_BS - 1) g_bsum[blockIdx.x] = s[t];
}

__global__ void k_scan23() {
    __shared__ int s[256];
    __shared__ int e[256];
    int t = threadIdx.x;
    int v = (t < SCAN_NB) ? g_bsum[t] : 0;
    s[t] = v;
    __syncthreads();
#pragma unroll
    for (int off = 1; off < 256; off <<= 1) {
        int xx = (t >= off) ? s[t - off] : 0;
        __syncthreads();
        s[t] += xx;
        __syncthreads();
    }
    e[t] = s[t] - v;
    __syncthreads();
    for (int i = blockIdx.x * blockDim.x + t; i < NN; i += gridDim.x * blockDim.x) {
        int incl = g_rowptr[i + 1] + e[i / SCAN_BS];
        g_rowptr[i + 1] = incl;
        g_cursor[i] = incl - g_cnt[i];
    }
    if (blockIdx.x == 0 && t == 0) g_rowptr[0] = 0;
}

__global__ void k_fill(const int* __restrict__ src, const int* __restrict__ dst) {
    int e = blockIdx.x * blockDim.x + threadIdx.x;
    if (e < BBG * HH) { g_gsum[e] = 0.0f; g_gmax[e] = 0u; }
    if (e < BBG) g_gcnt[e] = 0;
    if (e < EE) {
        int d = dst[e];
        int p = atomicAdd(&g_cursor[d], 1);
        g_col[p] = src[e];
    }
}

// ---------------- bf16 gather mean aggregation ----------------
// Half-warp per node: 16 lanes x uint4 (8 bf16 feats) = 256B per edge.
__global__ void __launch_bounds__(256)
k_agg(const __nv_bfloat162* __restrict__ hb, float* __restrict__ agg) {
    int warp = threadIdx.x >> 5;
    int lane = threadIdx.x & 31;
    int half = lane >> 4, l16 = lane & 15;
    int node = blockIdx.x * 16 + warp * 2 + half;
    int beg = g_rowptr[node], end = g_rowptr[node + 1];

    float2 s0 = make_float2(0.f, 0.f), s1 = make_float2(0.f, 0.f);
    float2 s2 = make_float2(0.f, 0.f), s3 = make_float2(0.f, 0.f);

    int j = beg;
#pragma unroll 1
    for (; j + 4 <= end; j += 4) {
        int c0 = g_col[j], c1 = g_col[j + 1], c2 = g_col[j + 2], c3 = g_col[j + 3];
        uint4 v0 = *(const uint4*)(hb + (size_t)c0 * (HH / 2) + l16 * 4);
        uint4 v1 = *(const uint4*)(hb + (size_t)c1 * (HH / 2) + l16 * 4);
        uint4 v2 = *(const uint4*)(hb + (size_t)c2 * (HH / 2) + l16 * 4);
        uint4 v3 = *(const uint4*)(hb + (size_t)c3 * (HH / 2) + l16 * 4);
#pragma unroll
        for (int e = 0; e < 4; e++) {
            uint4 v = (e == 0) ? v0 : (e == 1) ? v1 : (e == 2) ? v2 : v3;
            float2 f0 = __bfloat1622float2(*(__nv_bfloat162*)&v.x);
            float2 f1 = __bfloat1622float2(*(__nv_bfloat162*)&v.y);
            float2 f2 = __bfloat1622float2(*(__nv_bfloat162*)&v.z);
            float2 f3 = __bfloat1622float2(*(__nv_bfloat162*)&v.w);
            s0.x += f0.x; s0.y += f0.y; s1.x += f1.x; s1.y += f1.y;
            s2.x += f2.x; s2.y += f2.y; s3.x += f3.x; s3.y += f3.y;
        }
    }
#pragma unroll 1
    for (; j < end; j++) {
        int c = g_col[j];
        uint4 v = *(const uint4*)(hb + (size_t)c * (HH / 2) + l16 * 4);
        float2 f0 = __bfloat1622float2(*(__nv_bfloat162*)&v.x);
        float2 f1 = __bfloat1622float2(*(__nv_bfloat162*)&v.y);
        float2 f2 = __bfloat1622float2(*(__nv_bfloat162*)&v.z);
        float2 f3 = __bfloat1622float2(*(__nv_bfloat162*)&v.w);
        s0.x += f0.x; s0.y += f0.y; s1.x += f1.x; s1.y += f1.y;
        s2.x += f2.x; s2.y += f2.y; s3.x += f3.x; s3.y += f3.y;
    }

    float inv = 1.0f / fmaxf((float)(end - beg), 1.0f);
    float4 o0 = make_float4(s0.x * inv, s0.y * inv, s1.x * inv, s1.y * inv);
    float4 o1 = make_float4(s2.x * inv, s2.y * inv, s3.x * inv, s3.y * inv);
    float* dst = agg + (size_t)node * HH + l16 * 8;
    *(float4*)(dst)     = o0;
    *(float4*)(dst + 4) = o1;
}

// ---------------- tf32 mma.sync dual-GEMM + LN + ReLU ----------------
// CTA: 128 nodes x 128 out-feats, K=256 (agg||h vs Wl||Wr), 8 warps in 2x4.
// Warp tile 64x32. m16n8k8 tf32 fragments, pair-permuted smem K layout.
// A operand is register-prefetched one chunk ahead; B (weights) is L1-hot.
// Epilogue writes fp32 out + optional bf16 mirror (for next layer's gather).
__global__ void __launch_bounds__(256, 2)
k_gemm_mma(const float* __restrict__ A, const float* __restrict__ Hin,
           const float* __restrict__ Wl, const float* __restrict__ bl,
           const float* __restrict__ Wr,
           const float* __restrict__ gam, const float* __restrict__ bet,
           float* __restrict__ out, __nv_bfloat162* __restrict__ outb, int nNodes)
{
    __shared__ float As[128 * AST];
    __shared__ float Bs[128 * AST];
    __shared__ float2 stats[4][128];

    int tid  = threadIdx.x;
    int lane = tid & 31, wid = tid >> 5;
    int warp_m = wid >> 2;           // 0..1
    int warp_n = wid & 3;            // 0..3
    int node0 = blockIdx.x * 128;
    int gq = lane >> 2;              // group (0..7)
    int tq = lane & 3;               // thread-in-group (0..3)

    int srow[2], sg[2], snode[2];
#pragma unroll
    for (int it = 0; it < 2; it++) {
        int gi = it * 256 + tid;
        srow[it] = gi >> 2;
        sg[it]   = gi & 3;
        int nd = node0 + srow[it];
        snode[it] = (nd >= nNodes) ? (nNodes - 1) : nd;
    }

    float acc[4][4][4];
#pragma unroll
    for (int m = 0; m < 4; m++)
#pragma unroll
        for (int n = 0; n < 4; n++)
#pragma unroll
            for (int r = 0; r < 4; r++) acc[m][n][r] = 0.0f;

    float4 paLo[2], paHi[2];
#pragma unroll
    for (int it = 0; it < 2; it++) {
        const float* pa = A + (size_t)snode[it] * HH + sg[it] * 8;
        paLo[it] = *(const float4*)pa;
        paHi[it] = *(const float4*)(pa + 4);
    }

#pragma unroll 1
    for (int c = 0; c < 8; c++) {
        const float* W = (c < 4) ? Wl : Wr;
        int k0 = (c & 3) * 32;

#pragma unroll
        for (int it = 0; it < 2; it++) {
            store_perm8(As + srow[it] * AST + sg[it] * 8, paLo[it], paHi[it]);
            const float* pb = W + (size_t)srow[it] * HH + k0 + sg[it] * 8;
            store_perm8(Bs + srow[it] * AST + sg[it] * 8,
                        *(const float4*)pb, *(const float4*)(pb + 4));
        }
        __syncthreads();

        if (c < 7) {
            int cn = c + 1;
            const float* srcA = (cn < 4) ? A : Hin;
            int k0n = (cn & 3) * 32;
#pragma unroll
            for (int it = 0; it < 2; it++) {
                const float* pa = srcA + (size_t)snode[it] * HH + k0n + sg[it] * 8;
                paLo[it] = *(const float4*)pa;
                paHi[it] = *(const float4*)(pa + 4);
            }
        }

#pragma unroll
        for (int s = 0; s < 4; s++) {
            uint32_t b0[4], b1[4];
#pragma unroll
            for (int n = 0; n < 4; n++) {
                float2 bv = *(const float2*)(Bs + (warp_n * 32 + n * 8 + gq) * AST + s * 8 + tq * 2);
                b0[n] = __float_as_uint(bv.x);
                b1[n] = __float_as_uint(bv.y);
            }
#pragma unroll
            for (int m = 0; m < 4; m++) {
                int rbase = warp_m * 64 + m * 16 + gq;
                float2 a02 = *(const float2*)(As + rbase * AST + s * 8 + tq * 2);
                float2 a13 = *(const float2*)(As + (rbase + 8) * AST + s * 8 + tq * 2);
                uint32_t ra0 = __float_as_uint(a02.x);
                uint32_t ra1 = __float_as_uint(a13.x);
                uint32_t ra2 = __float_as_uint(a02.y);
                uint32_t ra3 = __float_as_uint(a13.y);
#pragma unroll
                for (int n = 0; n < 4; n++)
                    mma_tf32(acc[m][n], ra0, ra1, ra2, ra3, b0[n], b1[n]);
            }
        }
        __syncthreads();
    }

    // ---- epilogue: bias + LN + ReLU ----
    float blv[4][2], gmv[4][2], btv[4][2];
#pragma unroll
    for (int n = 0; n < 4; n++) {
        int col = warp_n * 32 + n * 8 + 2 * tq;
        blv[n][0] = __ldg(bl + col);  blv[n][1] = __ldg(bl + col + 1);
        gmv[n][0] = __ldg(gam + col); gmv[n][1] = __ldg(gam + col + 1);
        btv[n][0] = __ldg(bet + col); btv[n][1] = __ldg(bet + col + 1);
    }

#pragma unroll
    for (int m = 0; m < 4; m++) {
#pragma unroll
        for (int rh = 0; rh < 2; rh++) {
            float s = 0.0f, q = 0.0f;
#pragma unroll
            for (int n = 0; n < 4; n++) {
                float v0 = acc[m][n][rh * 2 + 0] + blv[n][0];
                float v1 = acc[m][n][rh * 2 + 1] + blv[n][1];
                acc[m][n][rh * 2 + 0] = v0;
                acc[m][n][rh * 2 + 1] = v1;
                s += v0 + v1; q += v0 * v0 + v1 * v1;
            }
            s += __shfl_xor_sync(0xffffffffu, s, 1);
            q += __shfl_xor_sync(0xffffffffu, q, 1);
            s += __shfl_xor_sync(0xffffffffu, s, 2);
            q += __shfl_xor_sync(0xffffffffu, q, 2);
            if (tq == 0)
                stats[warp_n][warp_m * 64 + m * 16 + rh * 8 + gq] = make_float2(s, q);
        }
    }
    __syncthreads();

    if (tid < 128) {
        float2 p0 = stats[0][tid], p1 = stats[1][tid];
        float2 p2 = stats[2][tid], p3 = stats[3][tid];
        float s = p0.x + p1.x + p2.x + p3.x;
        float q = p0.y + p1.y + p2.y + p3.y;
        float m  = s * (1.0f / HH);
        float vv = q * (1.0f / HH) - m * m;
        stats[0][tid] = make_float2(m, rsqrtf(vv + EPSV));
    }
    __syncthreads();

#pragma unroll
    for (int m = 0; m < 4; m++) {
#pragma unroll
        for (int rh = 0; rh < 2; rh++) {
            int row = warp_m * 64 + m * 16 + rh * 8 + gq;
            int node = node0 + row;
            if (node >= nNodes) continue;
            float2 mr = stats[0][row];
            float mu = mr.x, rs = mr.y;
#pragma unroll
            for (int n = 0; n < 4; n++) {
                int col = warp_n * 32 + n * 8 + 2 * tq;
                float y0 = fmaxf((acc[m][n][rh * 2 + 0] - mu) * rs * gmv[n][0] + btv[n][0], 0.0f);
                float y1 = fmaxf((acc[m][n][rh * 2 + 1] - mu) * rs * gmv[n][1] + btv[n][1], 0.0f);
                *(float2*)(out + (size_t)node * HH + col) = make_float2(y0, y1);
                if (outb) {
                    __nv_bfloat162 bb = __floats2bfloat162_rn(y0, y1);
                    outb[(size_t)node * (HH / 2) + (col >> 1)] = bb;
                }
            }
        }
    }
}

// ---------------- pooling (register-accumulated; batch is sorted) ----------------
__global__ void k_pool(const float* __restrict__ ne, const int* __restrict__ batch) {
    int base = blockIdx.x * 128;
    int sub  = threadIdx.x >> 7;
    int f    = threadIdx.x & 127;
    float s = 0.0f, mx = 0.0f;
    int cur = -1, cnt = 0;
    for (int i = sub; i < 128; i += 2) {
        int node = base + i;
        if (node >= NN) break;
        int b = batch[node];
        if (b != cur) {
            if (cur >= 0) {
                atomicAdd(&g_gsum[cur * HH + f], s);
                atomicMax(&g_gmax[cur * HH + f], __float_as_uint(mx));
                if (f == 0) atomicAdd(&g_gcnt[cur], cnt);
            }
            cur = b; s = 0.0f; mx = 0.0f; cnt = 0;
        }
        float v = ne[(size_t)node * HH + f];
        s += v; mx = fmaxf(mx, v); cnt++;
    }
    if (cur >= 0) {
        atomicAdd(&g_gsum[cur * HH + f], s);
        atomicMax(&g_gmax[cur * HH + f], __float_as_uint(mx));
        if (f == 0) atomicAdd(&g_gcnt[cur], cnt);
    }
}

__global__ void k_pool_final(float* __restrict__ out) {
    int b = blockIdx.x, f = threadIdx.x;
    float cnt = fmaxf((float)g_gcnt[b], 1.0f);
    out[(size_t)NN * HH + b * 2 * HH + f]      = g_gsum[b * HH + f] / cnt;
    out[(size_t)NN * HH + b * 2 * HH + HH + f] = __uint_as_float(g_gmax[b * HH + f]);
}

// ---------------- launch ----------------
extern "C" void kernel_launch(void* const* d_in, const int* in_sizes, int n_in,
                              void* d_out, int out_size)
{
    const float* x    = (const float*)d_in[0];
    const int*   ei   = (const int*)d_in[1];
    const int*   bat  = (const int*)d_in[2];
    const float* W0   = (const float*)d_in[3];
    const float* b0   = (const float*)d_in[4];
    const float* g0   = (const float*)d_in[5];
    const float* be0  = (const float*)d_in[6];
    const float* Wl1  = (const float*)d_in[7];
    const float* bl1  = (const float*)d_in[8];
    const float* Wr1  = (const float*)d_in[9];
    const float* g1   = (const float*)d_in[10];
    const float* be1  = (const float*)d_in[11];
    const float* Wl2  = (const float*)d_in[12];
    const float* bl2  = (const float*)d_in[13];
    const float* Wr2  = (const float*)d_in[14];
    const float* g2   = (const float*)d_in[15];
    const float* be2  = (const float*)d_in[16];
    const float* Wl3  = (const float*)d_in[17];
    const float* bl3  = (const float*)d_in[18];
    const float* Wr3  = (const float*)d_in[19];
    const float* g3   = (const float*)d_in[20];
    const float* be3  = (const float*)d_in[21];
    float* out = (float*)d_out;

    const int* src = ei;
    const int* dst = ei + EE;

    float* h0;  cudaGetSymbolAddress((void**)&h0,  g_h0);
    float* h1;  cudaGetSymbolAddress((void**)&h1,  g_h1);
    float* agg; cudaGetSymbolAddress((void**)&agg, g_agg);
    __nv_bfloat162* hb; cudaGetSymbolAddress((void**)&hb, g_hb);

    int nodeBlocks64  = (NN + 63) / 64;        // 1563
    int nodeBlocks128 = (NN + 127) / 128;      // 782
    int edgeBlocks    = (EE + 255) / 256;      // 6250
    int aggBlocks     = (NN + 15) / 16;        // 6250

    k_embed<<<nodeBlocks64, 256>>>(x, W0, b0, g0, be0, h0, hb, NN);

    k_count<<<edgeBlocks, 256>>>(dst);
    k_scan1<<<SCAN_NB, SCAN_BS>>>();
    k_scan23<<<256, 256>>>();
    k_fill<<<edgeBlocks, 256>>>(src, dst);

    // layer 1: h0 -> h1 (agg reads bf16 of h0)
    k_agg<<<aggBlocks, 256>>>(hb, agg);
    k_gemm_mma<<<nodeBlocks128, 256>>>(agg, h0, Wl1, bl1, Wr1, g1, be1, h1, hb, NN);
    // layer 2: h1 -> h0 (agg reads bf16 of h1)
    k_agg<<<aggBlocks, 256>>>(hb, agg);
    k_gemm_mma<<<nodeBlocks128, 256>>>(agg, h1, Wl2, bl2, Wr2, g2, be2, h0, hb, NN);
    // layer 3: h0 -> node_embed (agg reads bf16 of h0')
    k_agg<<<aggBlocks, 256>>>(hb, agg);
    k_gemm_mma<<<nodeBlocks128, 256>>>(agg, h0, Wl3, bl3, Wr3, g3, be3, out, nullptr, NN);

    // pooling
    k_pool<<<(NN + 127) / 128, 256>>>(out, bat);
    k_pool_final<<<BBG, HH>>>(out);
}